// round 1
// baseline (speedup 1.0000x reference)
#include <cuda_runtime.h>
#include <math.h>

#define NB 2048
#define ND 1024
#define NH 2048
#define NO 512
#define NE 8

#define BM 128
#define BN 128
#define BK 16

// Scratch (device globals: allocation-free kernel_launch)
__device__ float g_H[(size_t)NE * 2048 * NH];   // 128 MB expert hidden activations
__device__ float g_L[(size_t)NE * 2048 * NO];   // 32 MB expert logits
__device__ int   g_count[NE];
__device__ int   g_rows[NE * 2048];             // token index per expert slot
__device__ int   g_slot[NB * 2];                // (b,k) -> slot = e*2048+pos
__device__ float g_gate[NB * 2];

__global__ void zero_counts_kernel() {
    if (threadIdx.x < NE) g_count[threadIdx.x] = 0;
}

// One warp per token: logits = x @ w_gate, top-2 (first-index tie-break), softmax, scatter.
__global__ void gate_kernel(const float* __restrict__ x, const float* __restrict__ wg) {
    int warp = threadIdx.x >> 5;
    int lane = threadIdx.x & 31;
    int b = blockIdx.x * 8 + warp;
    float acc[NE];
#pragma unroll
    for (int e = 0; e < NE; e++) acc[e] = 0.f;
    const float* xr = x + (size_t)b * ND;
    for (int d = lane; d < ND; d += 32) {
        float xv = xr[d];
#pragma unroll
        for (int e = 0; e < NE; e++) acc[e] += xv * wg[d * NE + e];
    }
#pragma unroll
    for (int e = 0; e < NE; e++) {
#pragma unroll
        for (int off = 16; off; off >>= 1)
            acc[e] += __shfl_xor_sync(0xffffffffu, acc[e], off);
    }
    if (lane == 0) {
        int i0 = 0; float l0 = acc[0];
#pragma unroll
        for (int e = 1; e < NE; e++) if (acc[e] > l0) { l0 = acc[e]; i0 = e; }
        int i1 = (i0 == 0) ? 1 : 0;
        float l1 = acc[i1];
#pragma unroll
        for (int e = 0; e < NE; e++)
            if (e != i0 && acc[e] > l1) { l1 = acc[e]; i1 = e; }
        float ex = expf(l1 - l0);           // <= 1, stable
        float inv = 1.f / (1.f + ex);
        float gg0 = inv;
        float gg1 = ex * inv;
        int p0 = atomicAdd(&g_count[i0], 1);
        g_rows[i0 * 2048 + p0] = b;
        g_slot[b * 2 + 0] = i0 * 2048 + p0;
        g_gate[b * 2 + 0] = gg0;
        int p1 = atomicAdd(&g_count[i1], 1);
        g_rows[i1 * 2048 + p1] = b;
        g_slot[b * 2 + 1] = i1 * 2048 + p1;
        g_gate[b * 2 + 1] = gg1;
    }
}

// GEMM1: H[slot, h] = gelu( x[row, :] @ fc1_w[e] + fc1_b[e] ), gathered rows.
__global__ __launch_bounds__(256) void gemm1_kernel(
    const float* __restrict__ x, const float* __restrict__ w1, const float* __restrict__ b1)
{
    int e = blockIdx.z;
    int cnt = g_count[e];
    int t0 = blockIdx.y * BM;
    if (t0 >= cnt) return;
    int h0 = blockIdx.x * BN;

    __shared__ float As[BK][BM];
    __shared__ float Bs[BK][BN];
    __shared__ int rows[BM];

    int tid = threadIdx.x;
    if (tid < BM) rows[tid] = g_rows[e * 2048 + min(t0 + tid, cnt - 1)];
    __syncthreads();

    int tm = tid >> 4, tn = tid & 15;
    int a_r0 = tid >> 2, a_r1 = a_r0 + 64;
    int a_c = (tid & 3) * 4;
    int b_r0 = tid >> 5, b_r1 = b_r0 + 8;
    int b_c = (tid & 31) * 4;

    const float* Abase0 = x + (size_t)rows[a_r0] * ND + a_c;
    const float* Abase1 = x + (size_t)rows[a_r1] * ND + a_c;
    const float* Bbase  = w1 + (size_t)e * ND * NH + h0 + b_c;

    float acc[8][8];
#pragma unroll
    for (int i = 0; i < 8; i++)
#pragma unroll
        for (int j = 0; j < 8; j++) acc[i][j] = 0.f;

    for (int dk = 0; dk < ND; dk += BK) {
        float4 av0 = *(const float4*)(Abase0 + dk);
        float4 av1 = *(const float4*)(Abase1 + dk);
        float4 bv0 = *(const float4*)(Bbase + (size_t)(dk + b_r0) * NH);
        float4 bv1 = *(const float4*)(Bbase + (size_t)(dk + b_r1) * NH);
        __syncthreads();
        As[a_c + 0][a_r0] = av0.x; As[a_c + 1][a_r0] = av0.y;
        As[a_c + 2][a_r0] = av0.z; As[a_c + 3][a_r0] = av0.w;
        As[a_c + 0][a_r1] = av1.x; As[a_c + 1][a_r1] = av1.y;
        As[a_c + 2][a_r1] = av1.z; As[a_c + 3][a_r1] = av1.w;
        *(float4*)&Bs[b_r0][b_c] = bv0;
        *(float4*)&Bs[b_r1][b_c] = bv1;
        __syncthreads();
#pragma unroll
        for (int k = 0; k < BK; k++) {
            float a[8], bb[8];
            *(float4*)&a[0]  = *(const float4*)&As[k][tm * 8];
            *(float4*)&a[4]  = *(const float4*)&As[k][tm * 8 + 4];
            *(float4*)&bb[0] = *(const float4*)&Bs[k][tn * 8];
            *(float4*)&bb[4] = *(const float4*)&Bs[k][tn * 8 + 4];
#pragma unroll
            for (int i = 0; i < 8; i++)
#pragma unroll
                for (int j = 0; j < 8; j++)
                    acc[i][j] += a[i] * bb[j];
        }
    }

    float bias[8];
    *(float4*)&bias[0] = *(const float4*)(b1 + e * NH + h0 + tn * 8);
    *(float4*)&bias[4] = *(const float4*)(b1 + e * NH + h0 + tn * 8 + 4);
#pragma unroll
    for (int i = 0; i < 8; i++) {
        int r = t0 + tm * 8 + i;
        if (r < cnt) {
            float outv[8];
#pragma unroll
            for (int j = 0; j < 8; j++) {
                float v = acc[i][j] + bias[j];
                outv[j] = 0.5f * v * (1.0f + erff(v * 0.7071067811865476f));
            }
            float* dst = g_H + (size_t)(e * 2048 + r) * NH + h0 + tn * 8;
            *(float4*)dst       = *(float4*)&outv[0];
            *(float4*)(dst + 4) = *(float4*)&outv[4];
        }
    }
}

// GEMM2: L[slot, o] = H[slot, :] @ fc2_w[e] + fc2_b[e]
__global__ __launch_bounds__(256) void gemm2_kernel(
    const float* __restrict__ w2, const float* __restrict__ b2)
{
    int e = blockIdx.z;
    int cnt = g_count[e];
    int t0 = blockIdx.y * BM;
    if (t0 >= cnt) return;
    int o0 = blockIdx.x * BN;

    __shared__ float As[BK][BM];
    __shared__ float Bs[BK][BN];

    int tid = threadIdx.x;
    int tm = tid >> 4, tn = tid & 15;
    int a_r0 = tid >> 2, a_r1 = a_r0 + 64;
    int a_c = (tid & 3) * 4;
    int b_r0 = tid >> 5, b_r1 = b_r0 + 8;
    int b_c = (tid & 31) * 4;

    const float* Abase0 = g_H + (size_t)(e * 2048 + t0 + a_r0) * NH + a_c;
    const float* Abase1 = g_H + (size_t)(e * 2048 + t0 + a_r1) * NH + a_c;
    const float* Bbase  = w2 + (size_t)e * NH * NO + o0 + b_c;

    float acc[8][8];
#pragma unroll
    for (int i = 0; i < 8; i++)
#pragma unroll
        for (int j = 0; j < 8; j++) acc[i][j] = 0.f;

    for (int dk = 0; dk < NH; dk += BK) {
        float4 av0 = *(const float4*)(Abase0 + dk);
        float4 av1 = *(const float4*)(Abase1 + dk);
        float4 bv0 = *(const float4*)(Bbase + (size_t)(dk + b_r0) * NO);
        float4 bv1 = *(const float4*)(Bbase + (size_t)(dk + b_r1) * NO);
        __syncthreads();
        As[a_c + 0][a_r0] = av0.x; As[a_c + 1][a_r0] = av0.y;
        As[a_c + 2][a_r0] = av0.z; As[a_c + 3][a_r0] = av0.w;
        As[a_c + 0][a_r1] = av1.x; As[a_c + 1][a_r1] = av1.y;
        As[a_c + 2][a_r1] = av1.z; As[a_c + 3][a_r1] = av1.w;
        *(float4*)&Bs[b_r0][b_c] = bv0;
        *(float4*)&Bs[b_r1][b_c] = bv1;
        __syncthreads();
#pragma unroll
        for (int k = 0; k < BK; k++) {
            float a[8], bb[8];
            *(float4*)&a[0]  = *(const float4*)&As[k][tm * 8];
            *(float4*)&a[4]  = *(const float4*)&As[k][tm * 8 + 4];
            *(float4*)&bb[0] = *(const float4*)&Bs[k][tn * 8];
            *(float4*)&bb[4] = *(const float4*)&Bs[k][tn * 8 + 4];
#pragma unroll
            for (int i = 0; i < 8; i++)
#pragma unroll
                for (int j = 0; j < 8; j++)
                    acc[i][j] += a[i] * bb[j];
        }
    }

    float bias[8];
    *(float4*)&bias[0] = *(const float4*)(b2 + e * NO + o0 + tn * 8);
    *(float4*)&bias[4] = *(const float4*)(b2 + e * NO + o0 + tn * 8 + 4);
#pragma unroll
    for (int i = 0; i < 8; i++) {
        int r = t0 + tm * 8 + i;
        if (r < cnt) {
            float outv[8];
#pragma unroll
            for (int j = 0; j < 8; j++) outv[j] = acc[i][j] + bias[j];
            float* dst = g_L + (size_t)(e * 2048 + r) * NO + o0 + tn * 8;
            *(float4*)dst       = *(float4*)&outv[0];
            *(float4*)(dst + 4) = *(float4*)&outv[4];
        }
    }
}

// Per-token: logsumexp both expert rows, combine, log.
__global__ void combine_kernel(float* __restrict__ out) {
    int b = blockIdx.x;
    int tid = threadIdx.x;
    __shared__ float sred[256];

    int s0 = g_slot[b * 2], s1 = g_slot[b * 2 + 1];
    float gg0 = g_gate[b * 2], gg1 = g_gate[b * 2 + 1];
    const float* L0 = g_L + (size_t)s0 * NO;
    const float* L1 = g_L + (size_t)s1 * NO;
    float v00 = L0[tid], v01 = L0[tid + 256];
    float v10 = L1[tid], v11 = L1[tid + 256];

    sred[tid] = fmaxf(v00, v01); __syncthreads();
    for (int s = 128; s; s >>= 1) { if (tid < s) sred[tid] = fmaxf(sred[tid], sred[tid + s]); __syncthreads(); }
    float m0 = sred[0]; __syncthreads();
    sred[tid] = expf(v00 - m0) + expf(v01 - m0); __syncthreads();
    for (int s = 128; s; s >>= 1) { if (tid < s) sred[tid] += sred[tid + s]; __syncthreads(); }
    float lse0 = m0 + logf(sred[0]); __syncthreads();

    sred[tid] = fmaxf(v10, v11); __syncthreads();
    for (int s = 128; s; s >>= 1) { if (tid < s) sred[tid] = fmaxf(sred[tid], sred[tid + s]); __syncthreads(); }
    float m1 = sred[0]; __syncthreads();
    sred[tid] = expf(v10 - m1) + expf(v11 - m1); __syncthreads();
    for (int s = 128; s; s >>= 1) { if (tid < s) sred[tid] += sred[tid + s]; __syncthreads(); }
    float lse1 = m1 + logf(sred[0]);

    out[(size_t)b * NO + tid]       = logf(gg0 * expf(v00 - lse0) + gg1 * expf(v10 - lse1));
    out[(size_t)b * NO + tid + 256] = logf(gg0 * expf(v01 - lse0) + gg1 * expf(v11 - lse1));
}

extern "C" void kernel_launch(void* const* d_in, const int* in_sizes, int n_in,
                              void* d_out, int out_size) {
    const float* x  = (const float*)d_in[0];
    const float* wg = (const float*)d_in[1];
    const float* w1 = (const float*)d_in[2];
    const float* b1 = (const float*)d_in[3];
    const float* w2 = (const float*)d_in[4];
    const float* b2 = (const float*)d_in[5];
    float* out = (float*)d_out;

    zero_counts_kernel<<<1, 32>>>();
    gate_kernel<<<NB / 8, 256>>>(x, wg);
    dim3 g1(NH / BN, NB / BM, NE);
    gemm1_kernel<<<g1, 256>>>(x, w1, b1);
    dim3 g2(NO / BN, NB / BM, NE);
    gemm2_kernel<<<g2, 256>>>(w2, b2);
    combine_kernel<<<NB, 256>>>(out);
}

// round 3
// speedup vs baseline: 2.3282x; 2.3282x over previous
#include <cuda_runtime.h>
#include <math.h>
#include <stdint.h>

#define NB 2048
#define ND 1024
#define NH 2048
#define NO 512
#define NE 8

#define STAGES 3
#define A_STAGE_B (256 * 80)   // 256 rows * 20 words * 4B
#define B_STAGE_B (16 * 544)   // 16 k-rows * 136 words * 4B
#define SM_A 1024
#define SM_B (SM_A + STAGES * A_STAGE_B)
#define SMEM_TOTAL (SM_B + STAGES * B_STAGE_B)

// ---------------- scratch ----------------
__device__ float g_H[(size_t)NE * 2048 * NH];   // expert hidden (slot-major)
__device__ float g_L[(size_t)NE * 2048 * NO];   // expert logits
__device__ int   g_count[NE];
__device__ int   g_rows[NE * 2048];
__device__ int   g_slot[NB * 2];
__device__ float g_gate[NB * 2];

// ---------------- helpers ----------------
__device__ __forceinline__ uint32_t smem_to_u32(const void* p) {
    uint32_t a;
    asm("{ .reg .u64 t; cvta.to.shared.u64 t, %1; cvt.u32.u64 %0, t; }" : "=r"(a) : "l"(p));
    return a;
}
__device__ __forceinline__ void cpa16(uint32_t dst, const void* src) {
    asm volatile("cp.async.ca.shared.global [%0], [%1], 16;" :: "r"(dst), "l"(src));
}
#define CP_COMMIT() asm volatile("cp.async.commit_group;" ::: "memory")
#define CP_WAIT(n)  asm volatile("cp.async.wait_group %0;" :: "n"(n) : "memory")
__device__ __forceinline__ uint32_t lds32(uint32_t a) {
    uint32_t v;
    asm volatile("ld.shared.b32 %0, [%1];" : "=r"(v) : "r"(a));
    return v;
}
__device__ __forceinline__ void mma8(float* c, const uint32_t* a, const uint32_t* b) {
    asm volatile(
        "mma.sync.aligned.m16n8k8.row.col.f32.tf32.tf32.f32 "
        "{%0,%1,%2,%3}, {%4,%5,%6,%7}, {%8,%9}, {%0,%1,%2,%3};"
        : "+f"(c[0]), "+f"(c[1]), "+f"(c[2]), "+f"(c[3])
        : "r"(a[0]), "r"(a[1]), "r"(a[2]), "r"(a[3]), "r"(b[0]), "r"(b[1]));
}

__global__ void zero_counts_kernel() {
    if (threadIdx.x < NE) g_count[threadIdx.x] = 0;
}

// One warp per token: logits, top-2 (first-index ties), softmax-of-2, scatter.
__global__ void gate_kernel(const float* __restrict__ x, const float* __restrict__ wg) {
    int warp = threadIdx.x >> 5, lane = threadIdx.x & 31;
    int b = blockIdx.x * 8 + warp;
    float acc[NE];
#pragma unroll
    for (int e = 0; e < NE; e++) acc[e] = 0.f;
    const float* xr = x + (size_t)b * ND;
    for (int d = lane; d < ND; d += 32) {
        float xv = xr[d];
#pragma unroll
        for (int e = 0; e < NE; e++) acc[e] += xv * wg[d * NE + e];
    }
#pragma unroll
    for (int e = 0; e < NE; e++)
#pragma unroll
        for (int off = 16; off; off >>= 1)
            acc[e] += __shfl_xor_sync(0xffffffffu, acc[e], off);
    if (lane == 0) {
        int i0 = 0; float l0 = acc[0];
#pragma unroll
        for (int e = 1; e < NE; e++) if (acc[e] > l0) { l0 = acc[e]; i0 = e; }
        int i1 = (i0 == 0) ? 1 : 0;
        float l1 = acc[i1];
#pragma unroll
        for (int e = 0; e < NE; e++)
            if (e != i0 && acc[e] > l1) { l1 = acc[e]; i1 = e; }
        float ex = expf(l1 - l0);
        float inv = 1.f / (1.f + ex);
        int p0 = atomicAdd(&g_count[i0], 1);
        g_rows[i0 * 2048 + p0] = b;
        g_slot[b * 2 + 0] = i0 * 2048 + p0;
        g_gate[b * 2 + 0] = inv;
        int p1 = atomicAdd(&g_count[i1], 1);
        g_rows[i1 * 2048 + p1] = b;
        g_slot[b * 2 + 1] = i1 * 2048 + p1;
        g_gate[b * 2 + 1] = ex * inv;
    }
}

// ---------------- TF32 grouped GEMM: CTA 256x128, BK=16, 3-stage cp.async ----------------
// A row-major [M,K], B row-major [K,N] (consumed as col-major k x n fragments).
template <int KTOT, int LDA, int LDB, int LDC, bool LUT, bool GELU>
__global__ __launch_bounds__(256, 1) void gemm_tf32(
    const float* __restrict__ Ain,   // x (LUT) / unused
    const float* __restrict__ Bin,   // w1 / w2 (expert-major)
    const float* __restrict__ bias)  // b1 / b2
{
    int e = blockIdx.z;
    int cnt = g_count[e];
    int t0 = blockIdx.y * 256;
    if (t0 >= cnt) return;
    int n0 = blockIdx.x * 128;

    extern __shared__ char smem[];
    uint32_t sb = smem_to_u32(smem);
    int* rowsLUT = (int*)smem;
    int tid = threadIdx.x;
    int lane = tid & 31, wid = tid >> 5;
    int wm = wid >> 1, wn = wid & 1;

    if (LUT) rowsLUT[tid] = g_rows[e * 2048 + min(t0 + tid, cnt - 1)];
    __syncthreads();

    // cp.async source/dest setup
    const float* aptr[4];
    uint32_t adst[4];
#pragma unroll
    for (int i = 0; i < 4; i++) {
        int r = (tid >> 2) + 64 * i;
        const float* base;
        if (LUT) base = Ain + (size_t)rowsLUT[r] * LDA;
        else     base = (const float*)g_H + (size_t)(e * 2048 + t0 + r) * LDA;
        aptr[i] = base + (tid & 3) * 4;
        adst[i] = sb + SM_A + r * 80 + (tid & 3) * 16;
    }
    const float* Bsrc = Bin + (size_t)e * KTOT * LDB + n0 + (tid & 31) * 4;
    int kb = tid >> 5;
    const float* bptr[2];
    uint32_t bdst[2];
#pragma unroll
    for (int j = 0; j < 2; j++) {
        bptr[j] = Bsrc + (size_t)(kb + 8 * j) * LDB;
        bdst[j] = sb + SM_B + (kb + 8 * j) * 544 + (tid & 31) * 16;
    }

    float c[4][8][4];
#pragma unroll
    for (int mt = 0; mt < 4; mt++)
#pragma unroll
        for (int nt = 0; nt < 8; nt++)
#pragma unroll
            for (int q = 0; q < 4; q++) c[mt][nt][q] = 0.f;

    // prologue: stages 0..STAGES-2
#pragma unroll
    for (int s = 0; s < STAGES - 1; s++) {
        int k0 = s * 16;
#pragma unroll
        for (int i = 0; i < 4; i++) cpa16(adst[i] + s * A_STAGE_B, aptr[i] + k0);
#pragma unroll
        for (int j = 0; j < 2; j++) cpa16(bdst[j] + s * B_STAGE_B, bptr[j] + (size_t)k0 * LDB);
        CP_COMMIT();
    }

    uint32_t a_frag_base = sb + SM_A + ((wm * 64 + (lane >> 2)) * 20 + (lane & 3)) * 4;
    uint32_t b_frag_base = sb + SM_B + ((lane & 3) * 136 + wn * 64 + (lane >> 2)) * 4;

    const int NK = KTOT / 16;
    for (int kt = 0; kt < NK; kt++) {
        CP_WAIT(STAGES - 2);
        __syncthreads();
        int s = kt % STAGES;
        int knext = kt + STAGES - 1;
        if (knext < NK) {
            int sn = knext % STAGES;
            int k0 = knext * 16;
#pragma unroll
            for (int i = 0; i < 4; i++) cpa16(adst[i] + sn * A_STAGE_B, aptr[i] + k0);
#pragma unroll
            for (int j = 0; j < 2; j++) cpa16(bdst[j] + sn * B_STAGE_B, bptr[j] + (size_t)k0 * LDB);
            CP_COMMIT();
        }
        uint32_t ab = a_frag_base + s * A_STAGE_B;
        uint32_t bb = b_frag_base + s * B_STAGE_B;
#pragma unroll
        for (int ks = 0; ks < 2; ks++) {
            uint32_t af[4][4], bf[8][2];
#pragma unroll
            for (int mt = 0; mt < 4; mt++) {
                uint32_t ad = ab + mt * 1280 + ks * 32;
                af[mt][0] = lds32(ad);
                af[mt][1] = lds32(ad + 640);
                af[mt][2] = lds32(ad + 16);
                af[mt][3] = lds32(ad + 656);
            }
#pragma unroll
            for (int nt = 0; nt < 8; nt++) {
                uint32_t bd = bb + ks * 4352 + nt * 32;
                bf[nt][0] = lds32(bd);
                bf[nt][1] = lds32(bd + 2176);
            }
#pragma unroll
            for (int mt = 0; mt < 4; mt++)
#pragma unroll
                for (int nt = 0; nt < 8; nt++)
                    mma8(c[mt][nt], af[mt], bf[nt]);
        }
    }

    // epilogue: bias (+ gelu), write C in slot order
    float* Cbase = GELU ? g_H : g_L;
    float2 bv[8];
    const float* bias_e = bias + (size_t)e * LDC + n0 + wn * 64 + (lane & 3) * 2;
#pragma unroll
    for (int nt = 0; nt < 8; nt++) bv[nt] = *(const float2*)(bias_e + nt * 8);

#pragma unroll
    for (int mt = 0; mt < 4; mt++) {
#pragma unroll
        for (int h = 0; h < 2; h++) {
            int lr = wm * 64 + mt * 16 + (lane >> 2) + h * 8;
            if (t0 + lr < cnt) {
                float* dst = Cbase + (size_t)(e * 2048 + t0 + lr) * LDC + n0 + wn * 64 + (lane & 3) * 2;
#pragma unroll
                for (int nt = 0; nt < 8; nt++) {
                    float v0 = c[mt][nt][h * 2 + 0] + bv[nt].x;
                    float v1 = c[mt][nt][h * 2 + 1] + bv[nt].y;
                    if (GELU) {
                        v0 = 0.5f * v0 * (1.0f + erff(v0 * 0.7071067811865476f));
                        v1 = 0.5f * v1 * (1.0f + erff(v1 * 0.7071067811865476f));
                    }
                    *(float2*)(dst + nt * 8) = make_float2(v0, v1);
                }
            }
        }
    }
}

// Per-token: logsumexp both expert rows, combine, log.
__global__ void combine_kernel(float* __restrict__ out) {
    int b = blockIdx.x;
    int tid = threadIdx.x;
    __shared__ float sred[256];
    int s0 = g_slot[b * 2], s1 = g_slot[b * 2 + 1];
    float gg0 = g_gate[b * 2], gg1 = g_gate[b * 2 + 1];
    const float* L0 = g_L + (size_t)s0 * NO;
    const float* L1 = g_L + (size_t)s1 * NO;
    float v00 = L0[tid], v01 = L0[tid + 256];
    float v10 = L1[tid], v11 = L1[tid + 256];

    sred[tid] = fmaxf(v00, v01); __syncthreads();
    for (int s = 128; s; s >>= 1) { if (tid < s) sred[tid] = fmaxf(sred[tid], sred[tid + s]); __syncthreads(); }
    float m0 = sred[0]; __syncthreads();
    sred[tid] = expf(v00 - m0) + expf(v01 - m0); __syncthreads();
    for (int s = 128; s; s >>= 1) { if (tid < s) sred[tid] += sred[tid + s]; __syncthreads(); }
    float lse0 = m0 + logf(sred[0]); __syncthreads();

    sred[tid] = fmaxf(v10, v11); __syncthreads();
    for (int s = 128; s; s >>= 1) { if (tid < s) sred[tid] = fmaxf(sred[tid], sred[tid + s]); __syncthreads(); }
    float m1 = sred[0]; __syncthreads();
    sred[tid] = expf(v10 - m1) + expf(v11 - m1); __syncthreads();
    for (int s = 128; s; s >>= 1) { if (tid < s) sred[tid] += sred[tid + s]; __syncthreads(); }
    float lse1 = m1 + logf(sred[0]);

    out[(size_t)b * NO + tid]       = logf(gg0 * expf(v00 - lse0) + gg1 * expf(v10 - lse1));
    out[(size_t)b * NO + tid + 256] = logf(gg0 * expf(v01 - lse0) + gg1 * expf(v11 - lse1));
}

extern "C" void kernel_launch(void* const* d_in, const int* in_sizes, int n_in,
                              void* d_out, int out_size) {
    const float* x  = (const float*)d_in[0];
    const float* wg = (const float*)d_in[1];
    const float* w1 = (const float*)d_in[2];
    const float* b1 = (const float*)d_in[3];
    const float* w2 = (const float*)d_in[4];
    const float* b2 = (const float*)d_in[5];
    float* out = (float*)d_out;

    cudaFuncSetAttribute((const void*)gemm_tf32<ND, ND, NH, NH, true, true>,
                         cudaFuncAttributeMaxDynamicSharedMemorySize, SMEM_TOTAL);
    cudaFuncSetAttribute((const void*)gemm_tf32<NH, NH, NO, NO, false, false>,
                         cudaFuncAttributeMaxDynamicSharedMemorySize, SMEM_TOTAL);

    zero_counts_kernel<<<1, 32>>>();
    gate_kernel<<<NB / 8, 256>>>(x, wg);
    gemm_tf32<ND, ND, NH, NH, true, true><<<dim3(NH / 128, 8, NE), 256, SMEM_TOTAL>>>(x, w1, b1);
    gemm_tf32<NH, NH, NO, NO, false, false><<<dim3(NO / 128, 8, NE), 256, SMEM_TOTAL>>>(x, w2, b2);
    combine_kernel<<<NB, 256>>>(out);
}

// round 4
// speedup vs baseline: 2.5988x; 1.1163x over previous
#include <cuda_runtime.h>
#include <math.h>
#include <stdint.h>

#define NB 2048
#define ND 1024
#define NH 2048
#define NO 512
#define NE 8
#define KSPLIT2 4

#define STAGES 4
#define A_STAGE_B (256 * 80)   // 256 rows * 20 words * 4B
#define B_STAGE_B (16 * 544)   // 16 k-rows * 136 words * 4B
#define SM_A 1024
#define SM_B (SM_A + STAGES * A_STAGE_B)
#define SMEM_TOTAL (SM_B + STAGES * B_STAGE_B)

// ---------------- scratch ----------------
__device__ float g_H[(size_t)NE * 2048 * NH];                 // expert hidden (slot-major)
__device__ float g_Lp[(size_t)KSPLIT2 * NE * 2048 * NO];      // split-K partial logits
__device__ int   g_count[NE];
__device__ int   g_rows[NE * 2048];
__device__ int   g_slot[NB * 2];
__device__ float g_gate[NB * 2];

#define PARTSZ ((size_t)NE * 2048 * NO)

// ---------------- helpers ----------------
__device__ __forceinline__ uint32_t smem_to_u32(const void* p) {
    uint32_t a;
    asm("{ .reg .u64 t; cvta.to.shared.u64 t, %1; cvt.u32.u64 %0, t; }" : "=r"(a) : "l"(p));
    return a;
}
__device__ __forceinline__ void cpa16(uint32_t dst, const void* src) {
    asm volatile("cp.async.ca.shared.global [%0], [%1], 16;" :: "r"(dst), "l"(src));
}
#define CP_COMMIT() asm volatile("cp.async.commit_group;" ::: "memory")
#define CP_WAIT(n)  asm volatile("cp.async.wait_group %0;" :: "n"(n) : "memory")
__device__ __forceinline__ uint32_t lds32(uint32_t a) {
    uint32_t v;
    asm volatile("ld.shared.b32 %0, [%1];" : "=r"(v) : "r"(a));
    return v;
}
__device__ __forceinline__ void mma8(float* c, const uint32_t* a, const uint32_t* b) {
    asm volatile(
        "mma.sync.aligned.m16n8k8.row.col.f32.tf32.tf32.f32 "
        "{%0,%1,%2,%3}, {%4,%5,%6,%7}, {%8,%9}, {%0,%1,%2,%3};"
        : "+f"(c[0]), "+f"(c[1]), "+f"(c[2]), "+f"(c[3])
        : "r"(a[0]), "r"(a[1]), "r"(a[2]), "r"(a[3]), "r"(b[0]), "r"(b[1]));
}

__global__ void zero_counts_kernel() {
    if (threadIdx.x < NE) g_count[threadIdx.x] = 0;
}

// One warp per token: logits, top-2 (first-index ties), softmax-of-2, scatter.
__global__ void gate_kernel(const float* __restrict__ x, const float* __restrict__ wg) {
    int warp = threadIdx.x >> 5, lane = threadIdx.x & 31;
    int b = blockIdx.x * 8 + warp;
    float acc[NE];
#pragma unroll
    for (int e = 0; e < NE; e++) acc[e] = 0.f;
    const float* xr = x + (size_t)b * ND;
    for (int d = lane; d < ND; d += 32) {
        float xv = xr[d];
#pragma unroll
        for (int e = 0; e < NE; e++) acc[e] += xv * wg[d * NE + e];
    }
#pragma unroll
    for (int e = 0; e < NE; e++)
#pragma unroll
        for (int off = 16; off; off >>= 1)
            acc[e] += __shfl_xor_sync(0xffffffffu, acc[e], off);
    if (lane == 0) {
        int i0 = 0; float l0 = acc[0];
#pragma unroll
        for (int e = 1; e < NE; e++) if (acc[e] > l0) { l0 = acc[e]; i0 = e; }
        int i1 = (i0 == 0) ? 1 : 0;
        float l1 = acc[i1];
#pragma unroll
        for (int e = 0; e < NE; e++)
            if (e != i0 && acc[e] > l1) { l1 = acc[e]; i1 = e; }
        float ex = expf(l1 - l0);
        float inv = 1.f / (1.f + ex);
        int p0 = atomicAdd(&g_count[i0], 1);
        g_rows[i0 * 2048 + p0] = b;
        g_slot[b * 2 + 0] = i0 * 2048 + p0;
        g_gate[b * 2 + 0] = inv;
        int p1 = atomicAdd(&g_count[i1], 1);
        g_rows[i1 * 2048 + p1] = b;
        g_slot[b * 2 + 1] = i1 * 2048 + p1;
        g_gate[b * 2 + 1] = ex * inv;
    }
}

// ---------------- TF32 grouped GEMM: CTA 256x128, BK=16, multi-stage cp.async ----------------
// KCHUNK = K columns this CTA reduces; KFULL = full K of B (row stride context).
// KSPL = number of K splits (blockIdx.z = e * KSPL + ks).
template <int KCHUNK, int KFULL, int LDA, int LDB, int LDC, int KSPL, bool LUT, bool GELU>
__global__ __launch_bounds__(256, 1) void gemm_tf32(
    const float* __restrict__ Ain,   // x (LUT) / unused
    const float* __restrict__ Bin,   // w1 / w2 (expert-major)
    const float* __restrict__ bias)  // b1 (gemm2: unused)
{
    int e = blockIdx.z / KSPL;
    int ksp = blockIdx.z % KSPL;
    int cnt = g_count[e];
    int t0 = blockIdx.y * 256;
    if (t0 >= cnt) return;
    int n0 = blockIdx.x * 128;
    int kbase = ksp * KCHUNK;

    extern __shared__ char smem[];
    uint32_t sb = smem_to_u32(smem);
    int* rowsLUT = (int*)smem;
    int tid = threadIdx.x;
    int lane = tid & 31, wid = tid >> 5;
    int wm = wid >> 1, wn = wid & 1;

    if (LUT) rowsLUT[tid] = g_rows[e * 2048 + min(t0 + tid, cnt - 1)];
    __syncthreads();

    // cp.async source/dest setup
    const float* aptr[4];
    uint32_t adst[4];
#pragma unroll
    for (int i = 0; i < 4; i++) {
        int r = (tid >> 2) + 64 * i;
        const float* base;
        if (LUT) base = Ain + (size_t)rowsLUT[r] * LDA;
        else     base = (const float*)g_H + (size_t)(e * 2048 + t0 + r) * LDA;
        aptr[i] = base + kbase + (tid & 3) * 4;
        adst[i] = sb + SM_A + r * 80 + (tid & 3) * 16;
    }
    const float* Bsrc = Bin + (size_t)e * KFULL * LDB + (size_t)kbase * LDB + n0 + (tid & 31) * 4;
    int kb = tid >> 5;
    const float* bptr[2];
    uint32_t bdst[2];
#pragma unroll
    for (int j = 0; j < 2; j++) {
        bptr[j] = Bsrc + (size_t)(kb + 8 * j) * LDB;
        bdst[j] = sb + SM_B + (kb + 8 * j) * 544 + (tid & 31) * 16;
    }

    float c[4][8][4];
#pragma unroll
    for (int mt = 0; mt < 4; mt++)
#pragma unroll
        for (int nt = 0; nt < 8; nt++)
#pragma unroll
            for (int q = 0; q < 4; q++) c[mt][nt][q] = 0.f;

    // prologue: stages 0..STAGES-2
#pragma unroll
    for (int s = 0; s < STAGES - 1; s++) {
        int k0 = s * 16;
#pragma unroll
        for (int i = 0; i < 4; i++) cpa16(adst[i] + s * A_STAGE_B, aptr[i] + k0);
#pragma unroll
        for (int j = 0; j < 2; j++) cpa16(bdst[j] + s * B_STAGE_B, bptr[j] + (size_t)k0 * LDB);
        CP_COMMIT();
    }

    uint32_t a_frag_base = sb + SM_A + ((wm * 64 + (lane >> 2)) * 20 + (lane & 3)) * 4;
    uint32_t b_frag_base = sb + SM_B + ((lane & 3) * 136 + wn * 64 + (lane >> 2)) * 4;

    const int NK = KCHUNK / 16;
    for (int kt = 0; kt < NK; kt++) {
        CP_WAIT(STAGES - 2);
        __syncthreads();
        int s = kt % STAGES;
        int knext = kt + STAGES - 1;
        if (knext < NK) {
            int sn = knext % STAGES;
            int k0 = knext * 16;
#pragma unroll
            for (int i = 0; i < 4; i++) cpa16(adst[i] + sn * A_STAGE_B, aptr[i] + k0);
#pragma unroll
            for (int j = 0; j < 2; j++) cpa16(bdst[j] + sn * B_STAGE_B, bptr[j] + (size_t)k0 * LDB);
            CP_COMMIT();
        }
        uint32_t ab = a_frag_base + s * A_STAGE_B;
        uint32_t bb = b_frag_base + s * B_STAGE_B;
#pragma unroll
        for (int ks = 0; ks < 2; ks++) {
            uint32_t af[4][4], bf[8][2];
#pragma unroll
            for (int mt = 0; mt < 4; mt++) {
                uint32_t ad = ab + mt * 1280 + ks * 32;
                af[mt][0] = lds32(ad);
                af[mt][1] = lds32(ad + 640);
                af[mt][2] = lds32(ad + 16);
                af[mt][3] = lds32(ad + 656);
            }
#pragma unroll
            for (int nt = 0; nt < 8; nt++) {
                uint32_t bd = bb + ks * 4352 + nt * 32;
                bf[nt][0] = lds32(bd);
                bf[nt][1] = lds32(bd + 2176);
            }
#pragma unroll
            for (int mt = 0; mt < 4; mt++)
#pragma unroll
                for (int nt = 0; nt < 8; nt++)
                    mma8(c[mt][nt], af[mt], bf[nt]);
        }
    }

    // epilogue
#pragma unroll
    for (int mt = 0; mt < 4; mt++) {
#pragma unroll
        for (int h = 0; h < 2; h++) {
            int lr = wm * 64 + mt * 16 + (lane >> 2) + h * 8;
            if (t0 + lr < cnt) {
                size_t rowoff = (size_t)(e * 2048 + t0 + lr) * LDC + n0 + wn * 64 + (lane & 3) * 2;
                if (GELU) {
                    const float* bias_e = bias + (size_t)e * LDC + n0 + wn * 64 + (lane & 3) * 2;
                    float* dst = g_H + rowoff;
#pragma unroll
                    for (int nt = 0; nt < 8; nt++) {
                        float2 bv = *(const float2*)(bias_e + nt * 8);
                        float v0 = c[mt][nt][h * 2 + 0] + bv.x;
                        float v1 = c[mt][nt][h * 2 + 1] + bv.y;
                        v0 = 0.5f * v0 * (1.0f + erff(v0 * 0.7071067811865476f));
                        v1 = 0.5f * v1 * (1.0f + erff(v1 * 0.7071067811865476f));
                        *(float2*)(dst + nt * 8) = make_float2(v0, v1);
                    }
                } else {
                    float* dst = g_Lp + (size_t)ksp * PARTSZ + rowoff;
#pragma unroll
                    for (int nt = 0; nt < 8; nt++)
                        *(float2*)(dst + nt * 8) =
                            make_float2(c[mt][nt][h * 2 + 0], c[mt][nt][h * 2 + 1]);
                }
            }
        }
    }
}

// Per-token: sum split-K partials + bias, logsumexp both expert rows, combine, log.
__global__ void combine_kernel(float* __restrict__ out, const float* __restrict__ b2) {
    int b = blockIdx.x;
    int tid = threadIdx.x;
    __shared__ float sred[256];
    int s0 = g_slot[b * 2], s1 = g_slot[b * 2 + 1];
    int e0 = s0 >> 11, e1 = s1 >> 11;
    float gg0 = g_gate[b * 2], gg1 = g_gate[b * 2 + 1];

    float v00, v01, v10, v11;
    {
        size_t r0 = (size_t)s0 * NO, r1 = (size_t)s1 * NO;
        v00 = b2[e0 * NO + tid]; v01 = b2[e0 * NO + tid + 256];
        v10 = b2[e1 * NO + tid]; v11 = b2[e1 * NO + tid + 256];
#pragma unroll
        for (int p = 0; p < KSPLIT2; p++) {
            const float* P = g_Lp + (size_t)p * PARTSZ;
            v00 += P[r0 + tid]; v01 += P[r0 + tid + 256];
            v10 += P[r1 + tid]; v11 += P[r1 + tid + 256];
        }
    }

    sred[tid] = fmaxf(v00, v01); __syncthreads();
    for (int s = 128; s; s >>= 1) { if (tid < s) sred[tid] = fmaxf(sred[tid], sred[tid + s]); __syncthreads(); }
    float m0 = sred[0]; __syncthreads();
    sred[tid] = expf(v00 - m0) + expf(v01 - m0); __syncthreads();
    for (int s = 128; s; s >>= 1) { if (tid < s) sred[tid] += sred[tid + s]; __syncthreads(); }
    float lse0 = m0 + logf(sred[0]); __syncthreads();

    sred[tid] = fmaxf(v10, v11); __syncthreads();
    for (int s = 128; s; s >>= 1) { if (tid < s) sred[tid] = fmaxf(sred[tid], sred[tid + s]); __syncthreads(); }
    float m1 = sred[0]; __syncthreads();
    sred[tid] = expf(v10 - m1) + expf(v11 - m1); __syncthreads();
    for (int s = 128; s; s >>= 1) { if (tid < s) sred[tid] += sred[tid + s]; __syncthreads(); }
    float lse1 = m1 + logf(sred[0]);

    out[(size_t)b * NO + tid]       = logf(gg0 * expf(v00 - lse0) + gg1 * expf(v10 - lse1));
    out[(size_t)b * NO + tid + 256] = logf(gg0 * expf(v01 - lse0) + gg1 * expf(v11 - lse1));
}

extern "C" void kernel_launch(void* const* d_in, const int* in_sizes, int n_in,
                              void* d_out, int out_size) {
    const float* x  = (const float*)d_in[0];
    const float* wg = (const float*)d_in[1];
    const float* w1 = (const float*)d_in[2];
    const float* b1 = (const float*)d_in[3];
    const float* w2 = (const float*)d_in[4];
    const float* b2 = (const float*)d_in[5];
    float* out = (float*)d_out;

    auto k1 = gemm_tf32<ND, ND, ND, NH, NH, 1, true, true>;
    auto k2 = gemm_tf32<NH / KSPLIT2, NH, NH, NO, NO, KSPLIT2, false, false>;
    cudaFuncSetAttribute((const void*)k1, cudaFuncAttributeMaxDynamicSharedMemorySize, SMEM_TOTAL);
    cudaFuncSetAttribute((const void*)k2, cudaFuncAttributeMaxDynamicSharedMemorySize, SMEM_TOTAL);

    zero_counts_kernel<<<1, 32>>>();
    gate_kernel<<<NB / 8, 256>>>(x, wg);
    k1<<<dim3(NH / 128, 8, NE), 256, SMEM_TOTAL>>>(x, w1, b1);
    k2<<<dim3(NO / 128, 8, NE * KSPLIT2), 256, SMEM_TOTAL>>>(x, w2, b2);
    combine_kernel<<<NB, 256>>>(out, b2);
}